// round 10
// baseline (speedup 1.0000x reference)
#include <cuda_runtime.h>
#include <cuda_bf16.h>
#include <cuda_fp16.h>
#include <math.h>

// ---------------------------------------------------------------------------
// QuantumAttention, analytic circuit collapse:
//   z_i = cos(x_i + p_i); proj[0] = z1..z7 ; proj[w>=1] = z0..zw
// Fused proj+attention: each block computes its head's projections from x,
// then QK^T tf32 mma -> f16x2 ex2 softmax -> P@V f16 mma (+ ones-mma
// denominator), dual accumulator sets for ILP. Combine: split-tf32 GEMM.
// ---------------------------------------------------------------------------

#define NROWS   65536
#define S_LEN   1024
#define NHEADS  64
#define DK      8
#define E_DIM   128
#define NROWS_E 4096

__device__ float g_attn[NROWS_E * E_DIM]; // [b,s,e]
__device__ uint4 g_wb[16 * 16 * 32];      // W packed as split B-fragments

__device__ __forceinline__ unsigned tf32_of(float f) {
    unsigned u; asm("cvt.rna.tf32.f32 %0, %1;" : "=r"(u) : "f"(f));
    return u;
}
__device__ __forceinline__ unsigned h2_of(float lo, float hi) {
    __half2 h = __floats2half2_rn(lo, hi);
    return *reinterpret_cast<unsigned*>(&h);
}
__device__ __forceinline__ unsigned ex2_h2(unsigned s) {
    __half2 h = h2exp2(*reinterpret_cast<__half2*>(&s));
    return *reinterpret_cast<unsigned*>(&h);
}
// tf32 m16n8k8, C = A*B
__device__ __forceinline__ void mma8(float& c0, float& c1, float& c2, float& c3,
                                     unsigned a0, unsigned a1, unsigned a2, unsigned a3,
                                     unsigned b0, unsigned b1) {
    asm("mma.sync.aligned.m16n8k8.row.col.f32.tf32.tf32.f32 "
        "{%0,%1,%2,%3},{%4,%5,%6,%7},{%8,%9},{%10,%11,%12,%13};"
        : "=f"(c0), "=f"(c1), "=f"(c2), "=f"(c3)
        : "r"(a0), "r"(a1), "r"(a2), "r"(a3), "r"(b0), "r"(b1),
          "f"(0.f), "f"(0.f), "f"(0.f), "f"(0.f));
}
// tf32 m16n8k8, C += A*B
__device__ __forceinline__ void mma8_acc(float& c0, float& c1, float& c2, float& c3,
                                         unsigned a0, unsigned a1, unsigned a2, unsigned a3,
                                         unsigned b0, unsigned b1) {
    asm("mma.sync.aligned.m16n8k8.row.col.f32.tf32.tf32.f32 "
        "{%0,%1,%2,%3},{%4,%5,%6,%7},{%8,%9},{%0,%1,%2,%3};"
        : "+f"(c0), "+f"(c1), "+f"(c2), "+f"(c3)
        : "r"(a0), "r"(a1), "r"(a2), "r"(a3), "r"(b0), "r"(b1));
}
// f16 m16n8k16, C += A*B
__device__ __forceinline__ void mma16h_acc(float& c0, float& c1, float& c2, float& c3,
                                           unsigned a0, unsigned a1, unsigned a2, unsigned a3,
                                           unsigned b0, unsigned b1) {
    asm("mma.sync.aligned.m16n8k16.row.col.f32.f16.f16.f32 "
        "{%0,%1,%2,%3},{%4,%5,%6,%7},{%8,%9},{%0,%1,%2,%3};"
        : "+f"(c0), "+f"(c1), "+f"(c2), "+f"(c3)
        : "r"(a0), "r"(a1), "r"(a2), "r"(a3), "r"(b0), "r"(b1));
}

// 8-angle projection: z_i = cos(v_i + pv_i); o0 = z1..z7, o_w = z0..zw
__device__ __forceinline__ void proj8(float4 v0, float4 v1,
                                      const float* pv, float* o) {
    float z0 = __cosf(v0.x + pv[0]);
    float z1 = __cosf(v0.y + pv[1]);
    float z2 = __cosf(v0.z + pv[2]);
    float z3 = __cosf(v0.w + pv[3]);
    float z4 = __cosf(v1.x + pv[4]);
    float z5 = __cosf(v1.y + pv[5]);
    float z6 = __cosf(v1.z + pv[6]);
    float z7 = __cosf(v1.w + pv[7]);
    o[1] = z0 * z1;
    o[2] = o[1] * z2;
    o[3] = o[2] * z3;
    o[4] = o[3] * z4;
    o[5] = o[4] * z5;
    o[6] = o[5] * z6;
    o[7] = o[6] * z7;
    float t = z1 * z2;
    t *= z3; t *= z4; t *= z5; t *= z6; t *= z7;
    o[0] = t;
}

__global__ void nop_kernel() {}

// ---------------------------------------------------------------------------
// Fused proj + attention. Block = 256 threads, one (head, qt) pair.
// sKt: tf32, row r: [d0,d4, d1,d5, d2,d6, d3,d7]
// sVh: f16x2, pair j word d = (V[2j][d], V[2j+1][d])
// Dual accumulator sets (a/b) break the O/L dependency chains.
// ---------------------------------------------------------------------------
__global__ __launch_bounds__(256) void attn_kernel(const float* __restrict__ x,
                                                   const float* __restrict__ rx) {
    __shared__ __align__(16) unsigned sKt[S_LEN * DK];        // 32 KB
    __shared__ __align__(16) unsigned sVh[(S_LEN / 2) * DK];  // 16 KB

    int head = blockIdx.x >> 3;
    int qt   = blockIdx.x & 7;
    int tid  = threadIdx.x;
    int w    = tid >> 5;
    int lane = tid & 31;
    int g    = lane >> 2;
    int t4   = lane & 3;
    int bb_  = head >> 4;
    int hh   = head & 15;

    float pv[8];
#pragma unroll
    for (int i = 0; i < 8; i++) pv[i] = __ldg(rx + i);

    // ---- fused projection: rows 2j, 2j+1 from x; write sKt (tf32) + sVh ----
    const float4* x4 = reinterpret_cast<const float4*>(x);
#pragma unroll
    for (int i = 0; i < 2; i++) {
        int j = tid + i * 256;                       // pair index
        size_t r0 = ((size_t)((bb_ << 10) + 2 * j) << 4) + hh;  // angle-row of s=2j
        float4 a0 = x4[r0 * 2];
        float4 a1 = x4[r0 * 2 + 1];
        float4 c0 = x4[(r0 + 16) * 2];               // s = 2j+1
        float4 c1 = x4[(r0 + 16) * 2 + 1];

        float o[8], p[8];
        proj8(a0, a1, pv, o);
        proj8(c0, c1, pv, p);

        uint4* d0 = reinterpret_cast<uint4*>(sKt + (2 * j) * 8);
        d0[0] = make_uint4(tf32_of(o[0]), tf32_of(o[4]), tf32_of(o[1]), tf32_of(o[5]));
        d0[1] = make_uint4(tf32_of(o[2]), tf32_of(o[6]), tf32_of(o[3]), tf32_of(o[7]));
        uint4* d1 = reinterpret_cast<uint4*>(sKt + (2 * j + 1) * 8);
        d1[0] = make_uint4(tf32_of(p[0]), tf32_of(p[4]), tf32_of(p[1]), tf32_of(p[5]));
        d1[1] = make_uint4(tf32_of(p[2]), tf32_of(p[6]), tf32_of(p[3]), tf32_of(p[7]));
        uint4* vd = reinterpret_cast<uint4*>(sVh + j * 8);
        vd[0] = make_uint4(h2_of(o[0], p[0]), h2_of(o[1], p[1]),
                           h2_of(o[2], p[2]), h2_of(o[3], p[3]));
        vd[1] = make_uint4(h2_of(o[4], p[4]), h2_of(o[5], p[5]),
                           h2_of(o[6], p[6]), h2_of(o[7], p[7]));
    }
    __syncthreads();

    const float scale = 0.35355339059327373f * 1.4426950408889634f; // log2e/sqrt8

    // ---- Q A-frag (m16n8k8): rows g, g+8 of this warp's 16-row tile ----
    int ar = qt * 128 + w * 16 + g;
    uint2 q0 = *reinterpret_cast<const uint2*>(sKt + ar * 8 + 2 * t4);
    uint2 q1 = *reinterpret_cast<const uint2*>(sKt + (ar + 8) * 8 + 2 * t4);
    unsigned A0 = tf32_of(__uint_as_float(q0.x) * scale);
    unsigned A1 = tf32_of(__uint_as_float(q1.x) * scale);
    unsigned A2 = tf32_of(__uint_as_float(q0.y) * scale);
    unsigned A3 = tf32_of(__uint_as_float(q1.y) * scale);

    // dual accumulator sets
    float Oa0 = 0.f, Oa1 = 0.f, Oa2 = 0.f, Oa3 = 0.f;
    float Ob0 = 0.f, Ob1 = 0.f, Ob2 = 0.f, Ob3 = 0.f;
    float La0 = 0.f, La1 = 0.f, La2 = 0.f, La3 = 0.f;
    float Lb0 = 0.f, Lb1 = 0.f, Lb2 = 0.f, Lb3 = 0.f;
    const unsigned BONE = 0x3C003C00u;

#pragma unroll 2
    for (int kb = 0; kb < S_LEN; kb += 32) {
        // hoist all shared loads (max MLP)
        uint2 kf0 = *reinterpret_cast<const uint2*>(sKt + (kb      + g) * 8 + 2 * t4);
        uint2 kf1 = *reinterpret_cast<const uint2*>(sKt + (kb +  8 + g) * 8 + 2 * t4);
        uint2 kf2 = *reinterpret_cast<const uint2*>(sKt + (kb + 16 + g) * 8 + 2 * t4);
        uint2 kf3 = *reinterpret_cast<const uint2*>(sKt + (kb + 24 + g) * 8 + 2 * t4);
        unsigned vb0 = sVh[((kb >> 1)      + t4) * 8 + g];
        unsigned vb1 = sVh[((kb >> 1) +  4 + t4) * 8 + g];
        unsigned vb2 = sVh[((kb >> 1) +  8 + t4) * 8 + g];
        unsigned vb3 = sVh[((kb >> 1) + 12 + t4) * 8 + g];

        // chain A: keys kb .. kb+15
        float c0, c1, c2, c3, d0, d1, d2, d3;
        mma8(c0, c1, c2, c3, A0, A1, A2, A3, kf0.x, kf0.y);
        mma8(d0, d1, d2, d3, A0, A1, A2, A3, kf1.x, kf1.y);
        // chain B: keys kb+16 .. kb+31
        float u0, u1, u2, u3, v0, v1, v2, v3;
        mma8(u0, u1, u2, u3, A0, A1, A2, A3, kf2.x, kf2.y);
        mma8(v0, v1, v2, v3, A0, A1, A2, A3, kf3.x, kf3.y);

        unsigned pa01 = ex2_h2(h2_of(c0, c1));
        unsigned pa23 = ex2_h2(h2_of(c2, c3));
        unsigned ea01 = ex2_h2(h2_of(d0, d1));
        unsigned ea23 = ex2_h2(h2_of(d2, d3));
        unsigned pb01 = ex2_h2(h2_of(u0, u1));
        unsigned pb23 = ex2_h2(h2_of(u2, u3));
        unsigned eb01 = ex2_h2(h2_of(v0, v1));
        unsigned eb23 = ex2_h2(h2_of(v2, v3));

        mma16h_acc(Oa0, Oa1, Oa2, Oa3, pa01, pa23, ea01, ea23, vb0, vb1);
        mma16h_acc(Ob0, Ob1, Ob2, Ob3, pb01, pb23, eb01, eb23, vb2, vb3);
        mma16h_acc(La0, La1, La2, La3, pa01, pa23, ea01, ea23, BONE, BONE);
        mma16h_acc(Lb0, Lb1, Lb2, Lb3, pb01, pb23, eb01, eb23, BONE, BONE);
    }

    float O0 = Oa0 + Ob0, O1 = Oa1 + Ob1, O2 = Oa2 + Ob2, O3 = Oa3 + Ob3;
    float r0 = 1.0f / (La0 + Lb0);
    float r2 = 1.0f / (La2 + Lb2);

    int row = qt * 128 + w * 16 + g;
    size_t base = (size_t)((bb_ << 10) + row) * E_DIM + hh * DK + 2 * t4;

    *reinterpret_cast<float2*>(g_attn + base)              = make_float2(O0 * r0, O1 * r0);
    *reinterpret_cast<float2*>(g_attn + base + 8 * E_DIM)  = make_float2(O2 * r2, O3 * r2);
}

// ---------------------------------------------------------------------------
// Kernel 3a: pack W into split B-fragments (hi/lo tf32).
// ---------------------------------------------------------------------------
__global__ void pack_w(const float* __restrict__ W) {
    int j = blockIdx.x * blockDim.x + threadIdx.x;
    if (j >= 16 * 16 * 32) return;
    int lane = j & 31;
    int et   = (j >> 5) & 15;
    int kt   = j >> 9;
    int g    = lane >> 2;
    int t4   = lane & 3;
    int e = et * 8 + g;
    int k = kt * 8 + t4;
    float w0 = __ldg(W + e * E_DIM + k);
    float w1 = __ldg(W + e * E_DIM + k + 4);
    unsigned h0 = tf32_of(w0), h1 = tf32_of(w1);
    float l0 = w0 - __uint_as_float(h0);
    float l1 = w1 - __uint_as_float(h1);
    g_wb[j] = make_uint4(h0, h1, __float_as_uint(l0), __float_as_uint(l1));
}

// ---------------------------------------------------------------------------
// Kernel 3b: combine as split-tf32 GEMM (unchanged).
// ---------------------------------------------------------------------------
__global__ __launch_bounds__(256) void combine_kernel(float* __restrict__ out) {
    __shared__ __align__(16) float sa[32 * 132];

    int rb  = blockIdx.x >> 2;
    int eq  = blockIdx.x & 3;
    int row0 = rb * 32;
    int tid = threadIdx.x;
    int w   = tid >> 5;
    int lane = tid & 31;
    int g   = lane >> 2;
    int t4  = lane & 3;
    int rh  = w >> 2;
    int et  = w & 3;

    const float4* src = reinterpret_cast<const float4*>(g_attn + (size_t)row0 * E_DIM);
#pragma unroll
    for (int j = 0; j < 4; j++) {
        int idx = tid + j * 256;
        int r  = idx >> 5;
        int c4 = idx & 31;
        *reinterpret_cast<float4*>(sa + r * 132 + c4 * 4) = src[idx];
    }
    __syncthreads();

    float C0 = 0.f, C1 = 0.f, C2 = 0.f, C3 = 0.f;
    const float* sw = sa + (rh * 16 + g) * 132;

#pragma unroll
    for (int kt = 0; kt < 16; kt++) {
        int kb = kt * 8;
        float a0 = sw[kb + t4];
        float a1 = sw[8 * 132 + kb + t4];
        float a2 = sw[kb + t4 + 4];
        float a3 = sw[8 * 132 + kb + t4 + 4];
        unsigned h0 = tf32_of(a0), h1 = tf32_of(a1), h2 = tf32_of(a2), h3 = tf32_of(a3);
        unsigned l0 = __float_as_uint(a0 - __uint_as_float(h0));
        unsigned l1 = __float_as_uint(a1 - __uint_as_float(h1));
        unsigned l2 = __float_as_uint(a2 - __uint_as_float(h2));
        unsigned l3 = __float_as_uint(a3 - __uint_as_float(h3));

        uint4 B = __ldg(&g_wb[(kt * 16 + eq * 4 + et) * 32 + lane]);
        mma8_acc(C0, C1, C2, C3, h0, h1, h2, h3, B.x, B.y);
        mma8_acc(C0, C1, C2, C3, h0, h1, h2, h3, B.z, B.w);
        mma8_acc(C0, C1, C2, C3, l0, l1, l2, l3, B.x, B.y);
    }

    int r_g = row0 + rh * 16 + g;
    int e0  = eq * 32 + et * 8 + 2 * t4;
    *reinterpret_cast<float2*>(out + (size_t)r_g * E_DIM + e0) = make_float2(C0, C1);
    *reinterpret_cast<float2*>(out + (size_t)(r_g + 8) * E_DIM + e0) = make_float2(C2, C3);
}

// ---------------------------------------------------------------------------
extern "C" void kernel_launch(void* const* d_in, const int* in_sizes, int n_in,
                              void* d_out, int out_size) {
    const float* x  = nullptr;
    const float* rx = nullptr;
    const float* cw = nullptr;
    for (int i = 0; i < n_in; i++) {
        if (in_sizes[i] == NROWS * DK)          x  = (const float*)d_in[i];
        else if (in_sizes[i] == DK)             rx = (const float*)d_in[i];
        else if (in_sizes[i] == E_DIM * E_DIM)  cw = (const float*)d_in[i];
    }
    if (!x)  x  = (const float*)d_in[0];
    if (!rx) rx = (const float*)d_in[1];
    if (!cw) cw = (const float*)d_in[2];

    float* out = (float*)d_out;

    // attn placed 4th — the slot ncu has captured every round — to finally
    // profile it; nops are no-op padding.
    pack_w<<<(16 * 16 * 32 + 255) / 256, 256>>>(cw);
    nop_kernel<<<1, 32>>>();
    nop_kernel<<<1, 32>>>();
    attn_kernel<<<NHEADS * 8, 256>>>(x, rx);
    combine_kernel<<<512, 256>>>(out);
}

// round 11
// speedup vs baseline: 1.1053x; 1.1053x over previous
#include <cuda_runtime.h>
#include <cuda_bf16.h>
#include <cuda_fp16.h>
#include <math.h>

// ---------------------------------------------------------------------------
// QuantumAttention, analytic circuit collapse:
//   z_i = cos(x_i + p_i); proj[0] = z1..z7 ; proj[w>=1] = z0..zw
// qkv_pack: projections -> f16 K (pre-scaled by sqrt(log2e/sqrt(8))) and
// pair-interleaved f16 V, written once per head. attn: all-f16 tensor-pipe
// attention (QK m16n8k8.f16, ex2.f16x2 softmax, PV m16n8k16.f16 + ones-mma
// denominator). combine: split-tf32 GEMM, k-split across warp pairs.
// ---------------------------------------------------------------------------

#define NROWS   65536
#define S_LEN   1024
#define NHEADS  64
#define DK      8
#define E_DIM   128
#define NROWS_E 4096

__device__ float g_attn[NROWS_E * E_DIM]; // [b,s,e]
__device__ uint4 g_wb[16 * 16 * 32];      // W packed as split B-fragments
__device__ uint4 g_k16[NHEADS * S_LEN];   // f16x2 dim-pairs, pre-scaled (1 MB)
__device__ uint4 g_v16[NHEADS * (S_LEN / 2) * 2]; // f16x2 key-pair rows (1 MB)

__device__ __forceinline__ unsigned tf32_of(float f) {
    unsigned u; asm("cvt.rna.tf32.f32 %0, %1;" : "=r"(u) : "f"(f));
    return u;
}
__device__ __forceinline__ unsigned h2_of(float lo, float hi) {
    __half2 h = __floats2half2_rn(lo, hi);
    return *reinterpret_cast<unsigned*>(&h);
}
__device__ __forceinline__ unsigned ex2_h2(unsigned s) {
    __half2 h = h2exp2(*reinterpret_cast<__half2*>(&s));
    return *reinterpret_cast<unsigned*>(&h);
}
// f16 m16n8k8, C = A*B
__device__ __forceinline__ void mma8h(float& c0, float& c1, float& c2, float& c3,
                                      unsigned a0, unsigned a1, unsigned b0) {
    asm("mma.sync.aligned.m16n8k8.row.col.f32.f16.f16.f32 "
        "{%0,%1,%2,%3},{%4,%5},{%6},{%7,%8,%9,%10};"
        : "=f"(c0), "=f"(c1), "=f"(c2), "=f"(c3)
        : "r"(a0), "r"(a1), "r"(b0),
          "f"(0.f), "f"(0.f), "f"(0.f), "f"(0.f));
}
// f16 m16n8k16, C += A*B
__device__ __forceinline__ void mma16h_acc(float& c0, float& c1, float& c2, float& c3,
                                           unsigned a0, unsigned a1, unsigned a2, unsigned a3,
                                           unsigned b0, unsigned b1) {
    asm("mma.sync.aligned.m16n8k16.row.col.f32.f16.f16.f32 "
        "{%0,%1,%2,%3},{%4,%5,%6,%7},{%8,%9},{%0,%1,%2,%3};"
        : "+f"(c0), "+f"(c1), "+f"(c2), "+f"(c3)
        : "r"(a0), "r"(a1), "r"(a2), "r"(a3), "r"(b0), "r"(b1));
}
// tf32 m16n8k8, C += A*B
__device__ __forceinline__ void mma8_acc(float& c0, float& c1, float& c2, float& c3,
                                         unsigned a0, unsigned a1, unsigned a2, unsigned a3,
                                         unsigned b0, unsigned b1) {
    asm("mma.sync.aligned.m16n8k8.row.col.f32.tf32.tf32.f32 "
        "{%0,%1,%2,%3},{%4,%5,%6,%7},{%8,%9},{%0,%1,%2,%3};"
        : "+f"(c0), "+f"(c1), "+f"(c2), "+f"(c3)
        : "r"(a0), "r"(a1), "r"(a2), "r"(a3), "r"(b0), "r"(b1));
}

// 8-angle projection: z_i = cos(v_i + pv_i); o0 = z1..z7, o_w = z0..zw
__device__ __forceinline__ void proj8(float4 v0, float4 v1,
                                      const float* pv, float* o) {
    float z0 = __cosf(v0.x + pv[0]);
    float z1 = __cosf(v0.y + pv[1]);
    float z2 = __cosf(v0.z + pv[2]);
    float z3 = __cosf(v0.w + pv[3]);
    float z4 = __cosf(v1.x + pv[4]);
    float z5 = __cosf(v1.y + pv[5]);
    float z6 = __cosf(v1.z + pv[6]);
    float z7 = __cosf(v1.w + pv[7]);
    o[1] = z0 * z1;
    o[2] = o[1] * z2;
    o[3] = o[2] * z3;
    o[4] = o[3] * z4;
    o[5] = o[4] * z5;
    o[6] = o[5] * z6;
    o[7] = o[6] * z7;
    float t = z1 * z2;
    t *= z3; t *= z4; t *= z5; t *= z6; t *= z7;
    o[0] = t;
}

__global__ void nop_kernel() {}

// ---------------------------------------------------------------------------
// Kernel 1: projection + f16 packing (once per head, no redundancy).
// Thread = one key-pair (rows 2j, 2j+1 of one head).
// g_k16 row r: 4 f16x2 words = (d0,d1),(d2,d3),(d4,d5),(d6,d7) scaled by rs.
// g_v16 pair j: 8 f16x2 words, word d = (V[2j][d], V[2j+1][d]) unscaled.
// ---------------------------------------------------------------------------
__global__ void qkv_pack(const float* __restrict__ x,
                         const float* __restrict__ rx) {
    int r = blockIdx.x * blockDim.x + threadIdx.x;   // pair idx 0..32767
    if (r >= NHEADS * (S_LEN / 2)) return;
    int head = r >> 9;
    int j = r & 511;
    int bb = head >> 4;
    int hh = head & 15;

    float pv[8];
#pragma unroll
    for (int i = 0; i < 8; i++) pv[i] = __ldg(rx + i);

    const float4* x4 = reinterpret_cast<const float4*>(x);
    size_t r0 = ((size_t)((bb << 10) + 2 * j) << 4) + hh;
    float4 a0 = x4[r0 * 2];
    float4 a1 = x4[r0 * 2 + 1];
    float4 c0 = x4[(r0 + 16) * 2];
    float4 c1 = x4[(r0 + 16) * 2 + 1];

    float o[8], p[8];
    proj8(a0, a1, pv, o);
    proj8(c0, c1, pv, p);

    const float rs = 0.71421915f;   // sqrt(log2e / sqrt(8))

    g_k16[head * S_LEN + 2 * j] =
        make_uint4(h2_of(o[0] * rs, o[1] * rs), h2_of(o[2] * rs, o[3] * rs),
                   h2_of(o[4] * rs, o[5] * rs), h2_of(o[6] * rs, o[7] * rs));
    g_k16[head * S_LEN + 2 * j + 1] =
        make_uint4(h2_of(p[0] * rs, p[1] * rs), h2_of(p[2] * rs, p[3] * rs),
                   h2_of(p[4] * rs, p[5] * rs), h2_of(p[6] * rs, p[7] * rs));

    g_v16[(head * 512 + j) * 2] =
        make_uint4(h2_of(o[0], p[0]), h2_of(o[1], p[1]),
                   h2_of(o[2], p[2]), h2_of(o[3], p[3]));
    g_v16[(head * 512 + j) * 2 + 1] =
        make_uint4(h2_of(o[4], p[4]), h2_of(o[5], p[5]),
                   h2_of(o[6], p[6]), h2_of(o[7], p[7]));
}

// ---------------------------------------------------------------------------
// Kernel 2: all-f16 attention. Block = 256 threads, one (head, qt) pair.
// sK16 row r word t4 = (K[r][2t4], K[r][2t4+1]) pre-scaled  -> QK A and B.
// sVh  pair j word d = (V[2j][d], V[2j+1][d])               -> PV B.
// smem 32 KB, dual accumulator sets for ILP.
// ---------------------------------------------------------------------------
__global__ __launch_bounds__(256) void attn_kernel() {
    __shared__ __align__(16) unsigned sK16[S_LEN * 4];        // 16 KB
    __shared__ __align__(16) unsigned sVh[(S_LEN / 2) * DK];  // 16 KB

    int head = blockIdx.x >> 3;
    int qt   = blockIdx.x & 7;
    int tid  = threadIdx.x;
    int w    = tid >> 5;
    int lane = tid & 31;
    int g    = lane >> 2;
    int t4   = lane & 3;

    // coalesced copy of pre-packed K and V
    const uint4* Ksrc = g_k16 + head * S_LEN;
    const uint4* Vsrc = g_v16 + head * 1024;
    uint4* kd = reinterpret_cast<uint4*>(sK16);
    uint4* vd = reinterpret_cast<uint4*>(sVh);
#pragma unroll
    for (int i = 0; i < 4; i++) {
        int idx = tid + i * 256;
        kd[idx] = Ksrc[idx];
        vd[idx] = Vsrc[idx];
    }
    __syncthreads();

    // Q A-frag (m16n8k8.f16): rows ar, ar+8; already scaled
    int ar = qt * 128 + w * 16 + g;
    unsigned A0 = sK16[ar * 4 + t4];
    unsigned A1 = sK16[(ar + 8) * 4 + t4];

    float Oa0 = 0.f, Oa1 = 0.f, Oa2 = 0.f, Oa3 = 0.f;
    float Ob0 = 0.f, Ob1 = 0.f, Ob2 = 0.f, Ob3 = 0.f;
    float La0 = 0.f, La1 = 0.f, La2 = 0.f, La3 = 0.f;
    float Lb0 = 0.f, Lb1 = 0.f, Lb2 = 0.f, Lb3 = 0.f;
    const unsigned BONE = 0x3C003C00u;

#pragma unroll 2
    for (int kb = 0; kb < S_LEN; kb += 32) {
        unsigned kf0 = sK16[(kb      + g) * 4 + t4];
        unsigned kf1 = sK16[(kb +  8 + g) * 4 + t4];
        unsigned kf2 = sK16[(kb + 16 + g) * 4 + t4];
        unsigned kf3 = sK16[(kb + 24 + g) * 4 + t4];
        unsigned vb0 = sVh[((kb >> 1)      + t4) * 8 + g];
        unsigned vb1 = sVh[((kb >> 1) +  4 + t4) * 8 + g];
        unsigned vb2 = sVh[((kb >> 1) +  8 + t4) * 8 + g];
        unsigned vb3 = sVh[((kb >> 1) + 12 + t4) * 8 + g];

        float c0, c1, c2, c3, d0, d1, d2, d3;
        mma8h(c0, c1, c2, c3, A0, A1, kf0);
        mma8h(d0, d1, d2, d3, A0, A1, kf1);
        float u0, u1, u2, u3, v0, v1, v2, v3;
        mma8h(u0, u1, u2, u3, A0, A1, kf2);
        mma8h(v0, v1, v2, v3, A0, A1, kf3);

        unsigned pa01 = ex2_h2(h2_of(c0, c1));
        unsigned pa23 = ex2_h2(h2_of(c2, c3));
        unsigned ea01 = ex2_h2(h2_of(d0, d1));
        unsigned ea23 = ex2_h2(h2_of(d2, d3));
        unsigned pb01 = ex2_h2(h2_of(u0, u1));
        unsigned pb23 = ex2_h2(h2_of(u2, u3));
        unsigned eb01 = ex2_h2(h2_of(v0, v1));
        unsigned eb23 = ex2_h2(h2_of(v2, v3));

        mma16h_acc(Oa0, Oa1, Oa2, Oa3, pa01, pa23, ea01, ea23, vb0, vb1);
        mma16h_acc(Ob0, Ob1, Ob2, Ob3, pb01, pb23, eb01, eb23, vb2, vb3);
        mma16h_acc(La0, La1, La2, La3, pa01, pa23, ea01, ea23, BONE, BONE);
        mma16h_acc(Lb0, Lb1, Lb2, Lb3, pb01, pb23, eb01, eb23, BONE, BONE);
    }

    float O0 = Oa0 + Ob0, O1 = Oa1 + Ob1, O2 = Oa2 + Ob2, O3 = Oa3 + Ob3;
    float r0 = 1.0f / (La0 + Lb0);
    float r2 = 1.0f / (La2 + Lb2);

    int bb_ = head >> 4;
    int hh  = head & 15;
    int row = qt * 128 + w * 16 + g;
    size_t base = (size_t)((bb_ << 10) + row) * E_DIM + hh * DK + 2 * t4;

    *reinterpret_cast<float2*>(g_attn + base)              = make_float2(O0 * r0, O1 * r0);
    *reinterpret_cast<float2*>(g_attn + base + 8 * E_DIM)  = make_float2(O2 * r2, O3 * r2);
}

// ---------------------------------------------------------------------------
// Kernel 3a: pack W into split B-fragments (hi/lo tf32).
// ---------------------------------------------------------------------------
__global__ void pack_w(const float* __restrict__ W) {
    int j = blockIdx.x * blockDim.x + threadIdx.x;
    if (j >= 16 * 16 * 32) return;
    int lane = j & 31;
    int et   = (j >> 5) & 15;
    int kt   = j >> 9;
    int g    = lane >> 2;
    int t4   = lane & 3;
    int e = et * 8 + g;
    int k = kt * 8 + t4;
    float w0 = __ldg(W + e * E_DIM + k);
    float w1 = __ldg(W + e * E_DIM + k + 4);
    unsigned h0 = tf32_of(w0), h1 = tf32_of(w1);
    float l0 = w0 - __uint_as_float(h0);
    float l1 = w1 - __uint_as_float(h1);
    g_wb[j] = make_uint4(h0, h1, __float_as_uint(l0), __float_as_uint(l1));
}

// ---------------------------------------------------------------------------
// Kernel 3b: combine, k-split: block = 16 rows x 32 e, 8 warps =
// 4 e-tiles x 2 k-halves; smem-reduce. grid 1024 -> ~55 warps/SM.
// ---------------------------------------------------------------------------
__global__ __launch_bounds__(256) void combine_kernel(float* __restrict__ out) {
    __shared__ __align__(16) float sa[16 * 132];      // 8.25 KB
    __shared__ float sred[4 * 32 * 4];                // 2 KB

    int rb  = blockIdx.x >> 2;
    int eq  = blockIdx.x & 3;
    int row0 = rb * 16;
    int tid = threadIdx.x;
    int w   = tid >> 5;
    int lane = tid & 31;
    int g   = lane >> 2;
    int t4  = lane & 3;
    int et  = w & 3;
    int kh  = w >> 2;

    const float4* src = reinterpret_cast<const float4*>(g_attn + (size_t)row0 * E_DIM);
#pragma unroll
    for (int j = 0; j < 2; j++) {
        int idx = tid + j * 256;
        int r  = idx >> 5;
        int c4 = idx & 31;
        *reinterpret_cast<float4*>(sa + r * 132 + c4 * 4) = src[idx];
    }
    __syncthreads();

    float C0 = 0.f, C1 = 0.f, C2 = 0.f, C3 = 0.f;
    const float* sw = sa + g * 132;

#pragma unroll
    for (int kt = kh * 8; kt < kh * 8 + 8; kt++) {
        int kb = kt * 8;
        float a0 = sw[kb + t4];
        float a1 = sw[8 * 132 + kb + t4];
        float a2 = sw[kb + t4 + 4];
        float a3 = sw[8 * 132 + kb + t4 + 4];
        unsigned h0 = tf32_of(a0), h1 = tf32_of(a1), h2 = tf32_of(a2), h3 = tf32_of(a3);
        unsigned l0 = __float_as_uint(a0 - __uint_as_float(h0));
        unsigned l1 = __float_as_uint(a1 - __uint_as_float(h1));
        unsigned l2 = __float_as_uint(a2 - __uint_as_float(h2));
        unsigned l3 = __float_as_uint(a3 - __uint_as_float(h3));

        uint4 B = __ldg(&g_wb[(kt * 16 + eq * 4 + et) * 32 + lane]);
        mma8_acc(C0, C1, C2, C3, h0, h1, h2, h3, B.x, B.y);
        mma8_acc(C0, C1, C2, C3, h0, h1, h2, h3, B.z, B.w);
        mma8_acc(C0, C1, C2, C3, l0, l1, l2, l3, B.x, B.y);
    }

    if (kh == 1) {
        float* rp = sred + (et * 32 + lane) * 4;
        rp[0] = C0; rp[1] = C1; rp[2] = C2; rp[3] = C3;
    }
    __syncthreads();
    if (kh == 0) {
        const float* rp = sred + (et * 32 + lane) * 4;
        C0 += rp[0]; C1 += rp[1]; C2 += rp[2]; C3 += rp[3];
        int r_g = row0 + g;
        int e0  = eq * 32 + et * 8 + 2 * t4;
        *reinterpret_cast<float2*>(out + (size_t)r_g * E_DIM + e0) = make_float2(C0, C1);
        *reinterpret_cast<float2*>(out + (size_t)(r_g + 8) * E_DIM + e0) = make_float2(C2, C3);
    }
}

// ---------------------------------------------------------------------------
extern "C" void kernel_launch(void* const* d_in, const int* in_sizes, int n_in,
                              void* d_out, int out_size) {
    const float* x  = nullptr;
    const float* rx = nullptr;
    const float* cw = nullptr;
    for (int i = 0; i < n_in; i++) {
        if (in_sizes[i] == NROWS * DK)          x  = (const float*)d_in[i];
        else if (in_sizes[i] == DK)             rx = (const float*)d_in[i];
        else if (in_sizes[i] == E_DIM * E_DIM)  cw = (const float*)d_in[i];
    }
    if (!x)  x  = (const float*)d_in[0];
    if (!rx) rx = (const float*)d_in[1];
    if (!cw) cw = (const float*)d_in[2];

    float* out = (float*)d_out;

    // attn kept 4th — the launch slot ncu captures.
    pack_w<<<(16 * 16 * 32 + 255) / 256, 256>>>(cw);
    qkv_pack<<<NHEADS * (S_LEN / 2) / 256, 256>>>(x, rx);
    nop_kernel<<<1, 32>>>();
    attn_kernel<<<NHEADS * 8, 256>>>();
    combine_kernel<<<1024, 256>>>(out);
}

// round 12
// speedup vs baseline: 1.1657x; 1.0546x over previous
#include <cuda_runtime.h>
#include <cuda_bf16.h>
#include <cuda_fp16.h>
#include <math.h>

// ---------------------------------------------------------------------------
// QuantumAttention, analytic circuit collapse:
//   z_i = cos(x_i + p_i); proj[0] = z1..z7 ; proj[w>=1] = z0..zw
// qkv_pack: projections -> f16 K (pre-scaled) + pair-interleaved f16 V.
// attn: all-f16 tensor-pipe attention, SPLIT-K over 2 key halves (grid 1024),
// unnormalized partials + denominators to global planes (linear combine,
// softmax has no running max). combine: split-tf32 GEMM; normalization
// (O0+O1)/(L0+L1) fused into its staging loop.
// ---------------------------------------------------------------------------

#define NROWS   65536
#define S_LEN   1024
#define NHEADS  64
#define DK      8
#define E_DIM   128
#define NROWS_E 4096

__device__ float g_po[2 * NROWS_E * E_DIM];       // unnormalized O partials (4 MB)
__device__ float g_pl[2 * NROWS_E * 16];          // denominator partials (512 KB)
__device__ uint4 g_wb[16 * 16 * 32];              // W split B-fragments
__device__ uint4 g_k16[NHEADS * S_LEN];           // f16x2 dim-pairs, pre-scaled
__device__ uint4 g_v16[NHEADS * (S_LEN / 2) * 2]; // f16x2 key-pair rows

__device__ __forceinline__ unsigned tf32_of(float f) {
    unsigned u; asm("cvt.rna.tf32.f32 %0, %1;" : "=r"(u) : "f"(f));
    return u;
}
__device__ __forceinline__ unsigned h2_of(float lo, float hi) {
    __half2 h = __floats2half2_rn(lo, hi);
    return *reinterpret_cast<unsigned*>(&h);
}
__device__ __forceinline__ unsigned ex2_h2(unsigned s) {
    __half2 h = h2exp2(*reinterpret_cast<__half2*>(&s));
    return *reinterpret_cast<unsigned*>(&h);
}
// f16 m16n8k8, C = A*B
__device__ __forceinline__ void mma8h(float& c0, float& c1, float& c2, float& c3,
                                      unsigned a0, unsigned a1, unsigned b0) {
    asm("mma.sync.aligned.m16n8k8.row.col.f32.f16.f16.f32 "
        "{%0,%1,%2,%3},{%4,%5},{%6},{%7,%8,%9,%10};"
        : "=f"(c0), "=f"(c1), "=f"(c2), "=f"(c3)
        : "r"(a0), "r"(a1), "r"(b0),
          "f"(0.f), "f"(0.f), "f"(0.f), "f"(0.f));
}
// f16 m16n8k16, C += A*B
__device__ __forceinline__ void mma16h_acc(float& c0, float& c1, float& c2, float& c3,
                                           unsigned a0, unsigned a1, unsigned a2, unsigned a3,
                                           unsigned b0, unsigned b1) {
    asm("mma.sync.aligned.m16n8k16.row.col.f32.f16.f16.f32 "
        "{%0,%1,%2,%3},{%4,%5,%6,%7},{%8,%9},{%0,%1,%2,%3};"
        : "+f"(c0), "+f"(c1), "+f"(c2), "+f"(c3)
        : "r"(a0), "r"(a1), "r"(a2), "r"(a3), "r"(b0), "r"(b1));
}
// tf32 m16n8k8, C += A*B
__device__ __forceinline__ void mma8_acc(float& c0, float& c1, float& c2, float& c3,
                                         unsigned a0, unsigned a1, unsigned a2, unsigned a3,
                                         unsigned b0, unsigned b1) {
    asm("mma.sync.aligned.m16n8k8.row.col.f32.tf32.tf32.f32 "
        "{%0,%1,%2,%3},{%4,%5,%6,%7},{%8,%9},{%0,%1,%2,%3};"
        : "+f"(c0), "+f"(c1), "+f"(c2), "+f"(c3)
        : "r"(a0), "r"(a1), "r"(a2), "r"(a3), "r"(b0), "r"(b1));
}

__device__ __forceinline__ void proj8(float4 v0, float4 v1,
                                      const float* pv, float* o) {
    float z0 = __cosf(v0.x + pv[0]);
    float z1 = __cosf(v0.y + pv[1]);
    float z2 = __cosf(v0.z + pv[2]);
    float z3 = __cosf(v0.w + pv[3]);
    float z4 = __cosf(v1.x + pv[4]);
    float z5 = __cosf(v1.y + pv[5]);
    float z6 = __cosf(v1.z + pv[6]);
    float z7 = __cosf(v1.w + pv[7]);
    o[1] = z0 * z1;
    o[2] = o[1] * z2;
    o[3] = o[2] * z3;
    o[4] = o[3] * z4;
    o[5] = o[4] * z5;
    o[6] = o[5] * z6;
    o[7] = o[6] * z7;
    float t = z1 * z2;
    t *= z3; t *= z4; t *= z5; t *= z6; t *= z7;
    o[0] = t;
}

__global__ void nop_kernel() {}

// ---------------------------------------------------------------------------
// Kernel 1: projection + f16 packing (once per head).
// ---------------------------------------------------------------------------
__global__ void qkv_pack(const float* __restrict__ x,
                         const float* __restrict__ rx) {
    int r = blockIdx.x * blockDim.x + threadIdx.x;   // pair idx
    if (r >= NHEADS * (S_LEN / 2)) return;
    int head = r >> 9;
    int j = r & 511;
    int bb = head >> 4;
    int hh = head & 15;

    float pv[8];
#pragma unroll
    for (int i = 0; i < 8; i++) pv[i] = __ldg(rx + i);

    const float4* x4 = reinterpret_cast<const float4*>(x);
    size_t r0 = ((size_t)((bb << 10) + 2 * j) << 4) + hh;
    float4 a0 = x4[r0 * 2];
    float4 a1 = x4[r0 * 2 + 1];
    float4 c0 = x4[(r0 + 16) * 2];
    float4 c1 = x4[(r0 + 16) * 2 + 1];

    float o[8], p[8];
    proj8(a0, a1, pv, o);
    proj8(c0, c1, pv, p);

    const float rs = 0.71421915f;   // sqrt(log2e / sqrt(8))

    g_k16[head * S_LEN + 2 * j] =
        make_uint4(h2_of(o[0] * rs, o[1] * rs), h2_of(o[2] * rs, o[3] * rs),
                   h2_of(o[4] * rs, o[5] * rs), h2_of(o[6] * rs, o[7] * rs));
    g_k16[head * S_LEN + 2 * j + 1] =
        make_uint4(h2_of(p[0] * rs, p[1] * rs), h2_of(p[2] * rs, p[3] * rs),
                   h2_of(p[4] * rs, p[5] * rs), h2_of(p[6] * rs, p[7] * rs));

    g_v16[(head * 512 + j) * 2] =
        make_uint4(h2_of(o[0], p[0]), h2_of(o[1], p[1]),
                   h2_of(o[2], p[2]), h2_of(o[3], p[3]));
    g_v16[(head * 512 + j) * 2 + 1] =
        make_uint4(h2_of(o[4], p[4]), h2_of(o[5], p[5]),
                   h2_of(o[6], p[6]), h2_of(o[7], p[7]));
}

// ---------------------------------------------------------------------------
// Kernel 2: split-K attention. blockIdx = head*16 + qt*2 + ks; 256 threads.
// Each block: 128 q rows x 512 keys (half), smem 16 KB, writes UNNORMALIZED
// O partial + denominator L to plane ks.
// ---------------------------------------------------------------------------
#define KSPLIT_LEN 512
__global__ __launch_bounds__(256) void attn_kernel() {
    __shared__ __align__(16) unsigned sK16[KSPLIT_LEN * 4];        // 8 KB
    __shared__ __align__(16) unsigned sVh[(KSPLIT_LEN / 2) * DK];  // 8 KB

    int bx   = blockIdx.x;
    int head = bx >> 4;
    int qt   = (bx >> 1) & 7;
    int ks   = bx & 1;
    int tid  = threadIdx.x;
    int w    = tid >> 5;
    int lane = tid & 31;
    int g    = lane >> 2;
    int t4   = lane & 3;

    // coalesced copy of this half's K and V
    const uint4* Ksrc = g_k16 + head * S_LEN + ks * KSPLIT_LEN;
    const uint4* Vsrc = g_v16 + (head * 512 + ks * 256) * 2;
    uint4* kd = reinterpret_cast<uint4*>(sK16);
    uint4* vd = reinterpret_cast<uint4*>(sVh);
#pragma unroll
    for (int i = 0; i < 2; i++) {
        int idx = tid + i * 256;
        kd[idx] = Ksrc[idx];
        vd[idx] = Vsrc[idx];
    }
    __syncthreads();

    // Q A-frag: q rows come from the full K table — load straight from global
    // (rows qt*128 + w*16 + g, +8; 2 LDG.32, L2-hot)
    int ar = qt * 128 + w * 16 + g;
    const unsigned* Kg = reinterpret_cast<const unsigned*>(g_k16 + head * S_LEN);
    unsigned A0 = __ldg(Kg + ar * 4 + t4);
    unsigned A1 = __ldg(Kg + (ar + 8) * 4 + t4);

    float Oa0 = 0.f, Oa1 = 0.f, Oa2 = 0.f, Oa3 = 0.f;
    float Ob0 = 0.f, Ob1 = 0.f, Ob2 = 0.f, Ob3 = 0.f;
    float La0 = 0.f, La1 = 0.f, La2 = 0.f, La3 = 0.f;
    float Lb0 = 0.f, Lb1 = 0.f, Lb2 = 0.f, Lb3 = 0.f;
    const unsigned BONE = 0x3C003C00u;

#pragma unroll 2
    for (int kb = 0; kb < KSPLIT_LEN; kb += 32) {
        unsigned kf0 = sK16[(kb      + g) * 4 + t4];
        unsigned kf1 = sK16[(kb +  8 + g) * 4 + t4];
        unsigned kf2 = sK16[(kb + 16 + g) * 4 + t4];
        unsigned kf3 = sK16[(kb + 24 + g) * 4 + t4];
        unsigned vb0 = sVh[((kb >> 1)      + t4) * 8 + g];
        unsigned vb1 = sVh[((kb >> 1) +  4 + t4) * 8 + g];
        unsigned vb2 = sVh[((kb >> 1) +  8 + t4) * 8 + g];
        unsigned vb3 = sVh[((kb >> 1) + 12 + t4) * 8 + g];

        float c0, c1, c2, c3, d0, d1, d2, d3;
        mma8h(c0, c1, c2, c3, A0, A1, kf0);
        mma8h(d0, d1, d2, d3, A0, A1, kf1);
        float u0, u1, u2, u3, v0, v1, v2, v3;
        mma8h(u0, u1, u2, u3, A0, A1, kf2);
        mma8h(v0, v1, v2, v3, A0, A1, kf3);

        unsigned pa01 = ex2_h2(h2_of(c0, c1));
        unsigned pa23 = ex2_h2(h2_of(c2, c3));
        unsigned ea01 = ex2_h2(h2_of(d0, d1));
        unsigned ea23 = ex2_h2(h2_of(d2, d3));
        unsigned pb01 = ex2_h2(h2_of(u0, u1));
        unsigned pb23 = ex2_h2(h2_of(u2, u3));
        unsigned eb01 = ex2_h2(h2_of(v0, v1));
        unsigned eb23 = ex2_h2(h2_of(v2, v3));

        mma16h_acc(Oa0, Oa1, Oa2, Oa3, pa01, pa23, ea01, ea23, vb0, vb1);
        mma16h_acc(Ob0, Ob1, Ob2, Ob3, pb01, pb23, eb01, eb23, vb2, vb3);
        mma16h_acc(La0, La1, La2, La3, pa01, pa23, ea01, ea23, BONE, BONE);
        mma16h_acc(Lb0, Lb1, Lb2, Lb3, pb01, pb23, eb01, eb23, BONE, BONE);
    }

    float O0 = Oa0 + Ob0, O1 = Oa1 + Ob1, O2 = Oa2 + Ob2, O3 = Oa3 + Ob3;

    int bb_ = head >> 4;
    int hh  = head & 15;
    int row = qt * 128 + w * 16 + g;
    int grow = (bb_ << 10) + row;
    size_t base = (size_t)ks * NROWS_E * E_DIM + (size_t)grow * E_DIM + hh * DK + 2 * t4;

    *reinterpret_cast<float2*>(g_po + base)              = make_float2(O0, O1);
    *reinterpret_cast<float2*>(g_po + base + 8 * E_DIM)  = make_float2(O2, O3);

    if (t4 == 0) {
        g_pl[ks * NROWS_E * 16 + grow * 16 + hh]       = La0 + Lb0;
        g_pl[ks * NROWS_E * 16 + (grow + 8) * 16 + hh] = La2 + Lb2;
    }
}

// ---------------------------------------------------------------------------
// Kernel 3a: pack W into split B-fragments (hi/lo tf32).
// ---------------------------------------------------------------------------
__global__ void pack_w(const float* __restrict__ W) {
    int j = blockIdx.x * blockDim.x + threadIdx.x;
    if (j >= 16 * 16 * 32) return;
    int lane = j & 31;
    int et   = (j >> 5) & 15;
    int kt   = j >> 9;
    int g    = lane >> 2;
    int t4   = lane & 3;
    int e = et * 8 + g;
    int k = kt * 8 + t4;
    float w0 = __ldg(W + e * E_DIM + k);
    float w1 = __ldg(W + e * E_DIM + k + 4);
    unsigned h0 = tf32_of(w0), h1 = tf32_of(w1);
    float l0 = w0 - __uint_as_float(h0);
    float l1 = w1 - __uint_as_float(h1);
    g_wb[j] = make_uint4(h0, h1, __float_as_uint(l0), __float_as_uint(l1));
}

// ---------------------------------------------------------------------------
// Kernel 3b: combine. Staging fuses split-K reduction + normalization:
//   a[r][e] = (O0[r][e] + O1[r][e]) / (L0[r][h] + L1[r][h])
// then split-tf32 GEMM, k-split across warp pairs (grid 1024).
// ---------------------------------------------------------------------------
__global__ __launch_bounds__(256) void combine_kernel(float* __restrict__ out) {
    __shared__ __align__(16) float sa[16 * 132];
    __shared__ float sred[4 * 32 * 4];

    int rb  = blockIdx.x >> 2;
    int eq  = blockIdx.x & 3;
    int row0 = rb * 16;
    int tid = threadIdx.x;
    int w   = tid >> 5;
    int lane = tid & 31;
    int g   = lane >> 2;
    int t4  = lane & 3;
    int et  = w & 3;
    int kh  = w >> 2;

    const float4* p0 = reinterpret_cast<const float4*>(g_po + (size_t)row0 * E_DIM);
    const float4* p1 = reinterpret_cast<const float4*>(g_po + (size_t)NROWS_E * E_DIM
                                                       + (size_t)row0 * E_DIM);
#pragma unroll
    for (int j = 0; j < 2; j++) {
        int idx = tid + j * 256;
        int r  = idx >> 5;
        int c4 = idx & 31;
        float4 a = p0[idx];
        float4 b = p1[idx];
        int hh = c4 >> 1;
        float l = g_pl[(row0 + r) * 16 + hh] +
                  g_pl[NROWS_E * 16 + (row0 + r) * 16 + hh];
        float rinv = 1.0f / l;
        *reinterpret_cast<float4*>(sa + r * 132 + c4 * 4) =
            make_float4((a.x + b.x) * rinv, (a.y + b.y) * rinv,
                        (a.z + b.z) * rinv, (a.w + b.w) * rinv);
    }
    __syncthreads();

    float C0 = 0.f, C1 = 0.f, C2 = 0.f, C3 = 0.f;
    const float* sw = sa + g * 132;

#pragma unroll
    for (int kt = kh * 8; kt < kh * 8 + 8; kt++) {
        int kb = kt * 8;
        float a0 = sw[kb + t4];
        float a1 = sw[8 * 132 + kb + t4];
        float a2 = sw[kb + t4 + 4];
        float a3 = sw[8 * 132 + kb + t4 + 4];
        unsigned h0 = tf32_of(a0), h1 = tf32_of(a1), h2 = tf32_of(a2), h3 = tf32_of(a3);
        unsigned l0 = __float_as_uint(a0 - __uint_as_float(h0));
        unsigned l1 = __float_as_uint(a1 - __uint_as_float(h1));
        unsigned l2 = __float_as_uint(a2 - __uint_as_float(h2));
        unsigned l3 = __float_as_uint(a3 - __uint_as_float(h3));

        uint4 B = __ldg(&g_wb[(kt * 16 + eq * 4 + et) * 32 + lane]);
        mma8_acc(C0, C1, C2, C3, h0, h1, h2, h3, B.x, B.y);
        mma8_acc(C0, C1, C2, C3, h0, h1, h2, h3, B.z, B.w);
        mma8_acc(C0, C1, C2, C3, l0, l1, l2, l3, B.x, B.y);
    }

    if (kh == 1) {
        float* rp = sred + (et * 32 + lane) * 4;
        rp[0] = C0; rp[1] = C1; rp[2] = C2; rp[3] = C3;
    }
    __syncthreads();
    if (kh == 0) {
        const float* rp = sred + (et * 32 + lane) * 4;
        C0 += rp[0]; C1 += rp[1]; C2 += rp[2]; C3 += rp[3];
        int r_g = row0 + g;
        int e0  = eq * 32 + et * 8 + 2 * t4;
        *reinterpret_cast<float2*>(out + (size_t)r_g * E_DIM + e0) = make_float2(C0, C1);
        *reinterpret_cast<float2*>(out + (size_t)(r_g + 8) * E_DIM + e0) = make_float2(C2, C3);
    }
}

// ---------------------------------------------------------------------------
extern "C" void kernel_launch(void* const* d_in, const int* in_sizes, int n_in,
                              void* d_out, int out_size) {
    const float* x  = nullptr;
    const float* rx = nullptr;
    const float* cw = nullptr;
    for (int i = 0; i < n_in; i++) {
        if (in_sizes[i] == NROWS * DK)          x  = (const float*)d_in[i];
        else if (in_sizes[i] == DK)             rx = (const float*)d_in[i];
        else if (in_sizes[i] == E_DIM * E_DIM)  cw = (const float*)d_in[i];
    }
    if (!x)  x  = (const float*)d_in[0];
    if (!rx) rx = (const float*)d_in[1];
    if (!cw) cw = (const float*)d_in[2];

    float* out = (float*)d_out;

    // attn kept 4th — the launch slot ncu captures.
    pack_w<<<(16 * 16 * 32 + 255) / 256, 256>>>(cw);
    qkv_pack<<<NHEADS * (S_LEN / 2) / 256, 256>>>(x, rx);
    nop_kernel<<<1, 32>>>();
    attn_kernel<<<NHEADS * 16, 256>>>();
    combine_kernel<<<1024, 256>>>(out);
}